// round 11
// baseline (speedup 1.0000x reference)
#include <cuda_runtime.h>
#include <cuda_bf16.h>
#include <math.h>
#include <stdint.h>

typedef uint32_t u32;
typedef unsigned long long u64;

#define TT 256
#define BB 256
#define HH 1024
#define N2 2048
#define BMH (BB*HH)
#define NTHR 256
#define GBLK 128
#define CHU 1024                 /* uint4 per 16KB image block */
#define SMEMT 98304              /* 2 x 48KB chunk buffers (T64) */
#define SWZ(o) ((o) ^ (((o) >> 3) & 0x70))

/* fp32 states s0..s8 */
__device__ float g_S[9][BMH];
/* bf16 hi/lo swizzled images: states [st][mt][kc], x/h [mt][kc], W0 [nt*32+kc], Ws [op*256+nt*16+kc] */
__device__ uint4 g_Sih[288 * CHU], g_Sil[288 * CHU];
__device__ uint4 g_Xh[32 * CHU],  g_Xl[32 * CHU];
__device__ uint4 g_Hh[32 * CHU],  g_Hl[32 * CHU];
__device__ uint4 g_W0h[512 * CHU], g_W0l[512 * CHU];
__device__ uint4 g_Wsh[2048 * CHU], g_Wsl[2048 * CHU];
__device__ u64 g_bar;

/* ---------------- helpers ---------------- */
__device__ __forceinline__ float sigf(float v) { return 1.0f / (1.0f + expf(-v)); }
__device__ __forceinline__ float actf(float v, int a) {
    switch (a) { case 0: return sigf(v); case 1: return fmaxf(v, 0.0f);
                 case 2: return tanhf(v); default: return v; }
}
__device__ __forceinline__ u32 smem_u32(const void* p) {
    u32 a; asm("{ .reg .u64 t; cvta.to.shared.u64 t, %1; cvt.u32.u64 %0, t; }" : "=r"(a) : "l"(p));
    return a;
}
__device__ __forceinline__ void split8(const float* v, uint4& hi, uint4& lo) {
    u32 h[4], l[4];
#pragma unroll
    for (int p = 0; p < 4; p++) {
        __nv_bfloat16 b0 = __float2bfloat16(v[2*p]);
        __nv_bfloat16 b1 = __float2bfloat16(v[2*p+1]);
        __nv_bfloat16 c0 = __float2bfloat16(v[2*p]   - __bfloat162float(b0));
        __nv_bfloat16 c1 = __float2bfloat16(v[2*p+1] - __bfloat162float(b1));
        h[p] = (u32)__bfloat16_as_ushort(b0) | ((u32)__bfloat16_as_ushort(b1) << 16);
        l[p] = (u32)__bfloat16_as_ushort(c0) | ((u32)__bfloat16_as_ushort(c1) << 16);
    }
    hi = make_uint4(h[0], h[1], h[2], h[3]);
    lo = make_uint4(l[0], l[1], l[2], l[3]);
}
/* pack 2 fp32 -> hi/lo bf16x2 words */
__device__ __forceinline__ void split2(float s0, float s1, u32& hi, u32& lo) {
    __nv_bfloat16 b0 = __float2bfloat16(s0), b1 = __float2bfloat16(s1);
    __nv_bfloat16 c0 = __float2bfloat16(s0 - __bfloat162float(b0));
    __nv_bfloat16 c1 = __float2bfloat16(s1 - __bfloat162float(b1));
    hi = (u32)__bfloat16_as_ushort(b0) | ((u32)__bfloat16_as_ushort(b1) << 16);
    lo = (u32)__bfloat16_as_ushort(c0) | ((u32)__bfloat16_as_ushort(c1) << 16);
}

/* ---------------- warp MMA primitives ---------------- */
__device__ __forceinline__ void ldsm4(u32* d, u32 a) {
    asm volatile("ldmatrix.sync.aligned.m8n8.x4.shared.b16 {%0,%1,%2,%3}, [%4];"
        : "=r"(d[0]), "=r"(d[1]), "=r"(d[2]), "=r"(d[3]) : "r"(a));
}
__device__ __forceinline__ void ldsm2(u32* d, u32 a) {
    asm volatile("ldmatrix.sync.aligned.m8n8.x2.shared.b16 {%0,%1}, [%2];"
        : "=r"(d[0]), "=r"(d[1]) : "r"(a));
}
__device__ __forceinline__ void mma16816(float* c, const u32* a, const u32* b) {
    asm volatile("mma.sync.aligned.m16n8k16.row.col.f32.bf16.bf16.f32 "
        "{%0,%1,%2,%3}, {%4,%5,%6,%7}, {%8,%9}, {%0,%1,%2,%3};"
        : "+f"(c[0]), "+f"(c[1]), "+f"(c[2]), "+f"(c[3])
        : "r"(a[0]), "r"(a[1]), "r"(a[2]), "r"(a[3]), "r"(b[0]), "r"(b[1]));
}
#define CPA(dst, src) asm volatile("cp.async.cg.shared.global [%0], [%1], 16;" :: "r"(dst), "l"(src))
#define CPCOMMIT()    asm volatile("cp.async.commit_group;" ::: "memory")
#define CPWAIT(n)     asm volatile("cp.async.wait_group %0;" :: "n"(n) : "memory")

/* ---------------- grid barrier (monotonic, replay-safe) ---------------- */
__device__ __forceinline__ void gridbar() {
    __threadfence();
    __syncthreads();
    if (threadIdx.x == 0) {
        u64 t = atomicAdd(&g_bar, 1ULL);
        u64 goal = (t / GBLK + 1ULL) * (u64)GBLK;
        u64 v;
        do { asm volatile("ld.acquire.gpu.u64 %0, [%1];" : "=l"(v) : "l"(&g_bar) : "memory"); }
        while (v < goal);
    }
    __syncthreads();
}

/* ---------------- prep: build swizzled bf16 hi/lo images (unchanged, verified) ---------------- */
__global__ __launch_bounds__(NTHR) void prep(
    const float* __restrict__ inputs, const float* __restrict__ h0,
    const float* __restrict__ W0, const float* __restrict__ Ws)
{
    __shared__ float s[64][129];
    const int b = blockIdx.x, tid = threadIdx.x;

    if (b < 2560) {
        const float* Wsrc; int nt, kc; uint4 *dh, *dl;
        if (b < 512) {
            nt = b >> 5; kc = b & 31; Wsrc = W0;
            dh = g_W0h + (size_t)b * CHU; dl = g_W0l + (size_t)b * CHU;
        } else {
            int b2 = b - 512;
            nt = (b2 >> 4) & 15; kc = b2 & 15;
            Wsrc = Ws + (size_t)(b2 >> 8) * HH * N2;
            dh = g_Wsh + (size_t)b2 * CHU; dl = g_Wsl + (size_t)b2 * CHU;
        }
        for (int i = tid; i < 64 * 128; i += NTHR) {
            int k = i >> 7, r = i & 127;
            int n = (r < 64) ? nt * 64 + r : HH + nt * 64 + (r - 64);
            s[k][r] = Wsrc[(size_t)(kc * 64 + k) * N2 + n];
        }
        __syncthreads();
        for (int uu = tid; uu < 1024; uu += NTHR) {
            int r = uu >> 3, g = uu & 7;
            float v[8];
#pragma unroll
            for (int i = 0; i < 8; i++) v[i] = s[g * 8 + i][r];
            uint4 hi, lo; split8(v, hi, lo);
            u32 off = SWZ((u32)(r * 128 + g * 16));
            dh[off >> 4] = hi; dl[off >> 4] = lo;
        }
    } else {
        int b3 = b - 2560;
        const float* src = (b3 < 128) ? inputs : h0;
        uint4* dh = (b3 < 128) ? g_Xh : g_Hh;
        uint4* dl = (b3 < 128) ? g_Xl : g_Hl;
        int uu = (b3 & 127) * NTHR + tid;
        int g = uu & 7, r = (uu >> 3) & 127, kc = (uu >> 10) & 15, mt = uu >> 14;
        int m = mt * 128 + r, k = kc * 64 + g * 8;
        const float4* p = (const float4*)(src + (size_t)m * HH + k);
        float4 a = p[0], bq = p[1];
        float v[8] = {a.x, a.y, a.z, a.w, bq.x, bq.y, bq.z, bq.w};
        uint4 hi, lo; split8(v, hi, lo);
        u32 off = SWZ((u32)(r * 128 + g * 16));
        size_t blk = (size_t)(mt * 16 + kc) * CHU;
        dh[blk + (off >> 4)] = hi; dl[blk + (off >> 4)] = lo;
    }
}

/* ---------------- fused full-K GEMM tile + DARTS epilogue ----------------
 * MT rows x one 64-j W block (64 c-cols || 64 h-cols). 3-pass bf16 hi/lo MMA.
 * Interleaved warp N-layout so each thread owns matching (c, h) pairs ->
 * gate epilogue entirely in registers; writes fp32 state + optional bf16 image. */
template<int MT>
__device__ __noinline__ void run_tile(
    u32 sbase,
    const uint4* __restrict__ Ah0, const uint4* __restrict__ Al0,
    const uint4* __restrict__ Ah1, const uint4* __restrict__ Al1,
    int n1, int nchunks, int rowoff,
    const uint4* __restrict__ Wh, const uint4* __restrict__ Wl,
    const float* __restrict__ sp, float* __restrict__ Sout,
    uint4* imgH, uint4* imgL, int act, int m0, int j0)
{
    constexpr int NWN = (MT == 64) ? 4 : 8;   /* warps along N */
    constexpr int NFC = (MT == 64) ? 2 : 1;   /* c-frags (n8) per warp */
    constexpr int BS  = 2 * MT * 128 + 32768; /* bytes per chunk buffer */
    constexpr int AU  = MT * 8;               /* uint4 per A region */
    const int tid = threadIdx.x, lid = tid & 31, wid = tid >> 5;
    const int wm = wid / NWN, wn = wid % NWN;
    const int ncw = wn * (64 / NWN);

    float accC[2][NFC][4], accH[2][NFC][4];
#pragma unroll
    for (int i = 0; i < 2; i++)
#pragma unroll
        for (int j = 0; j < NFC; j++)
#pragma unroll
            for (int q = 0; q < 4; q++) { accC[i][j][q] = 0.f; accH[i][j][q] = 0.f; }

    const int arl = (lid & 7) + ((lid >> 3) & 1) * 8;
    const u32 aXor = (u32)((lid & 7) << 4);
    const u32 aK = (u32)((lid >> 4) * 16);
    const int lb = lid & 15;
    const u32 bXor = (u32)((lb & 7) << 4);
    const u32 bK = (u32)(((lb >> 3) & 1) * 16);
    const int brl = lb & 7;

    auto issue = [&](int c, int buf) {
        const uint4* Ahc = (c < n1) ? (Ah0 + (size_t)c * CHU) : (Ah1 + (size_t)(c - n1) * CHU);
        const uint4* Alc = (c < n1) ? (Al0 + (size_t)c * CHU) : (Al1 + (size_t)(c - n1) * CHU);
        const uint4* Wch = Wh + (size_t)c * CHU;
        const uint4* Wcl = Wl + (size_t)c * CHU;
        u32 d = sbase + (u32)buf * BS;
#pragma unroll
        for (int i = 0; i < AU / 256; i++)
            CPA(d + (u32)(tid + i * 256) * 16u, (const void*)(Ahc + rowoff + tid + i * 256));
#pragma unroll
        for (int i = 0; i < AU / 256; i++)
            CPA(d + (u32)MT * 128 + (u32)(tid + i * 256) * 16u, (const void*)(Alc + rowoff + tid + i * 256));
#pragma unroll
        for (int i = 0; i < 4; i++)
            CPA(d + 2u * MT * 128 + (u32)(tid + i * 256) * 16u, (const void*)(Wch + tid + i * 256));
#pragma unroll
        for (int i = 0; i < 4; i++)
            CPA(d + 2u * MT * 128 + 16384u + (u32)(tid + i * 256) * 16u, (const void*)(Wcl + tid + i * 256));
        CPCOMMIT();
    };

    issue(0, 0);
    if (nchunks > 1) issue(1, 1);
    int buf = 0;
    for (int ci = 0; ci < nchunks; ci++) {
        if (ci < nchunks - 1) { CPWAIT(1); } else { CPWAIT(0); }
        __syncthreads();
        u32 b0 = sbase + (u32)buf * BS;
        u32 wB = b0 + 2u * MT * 128;
#pragma unroll
        for (int ks = 0; ks < 4; ks++) {
            u32 ah[2][4], al[2][4];
            u32 ka = ((u32)(ks * 32) + aK) ^ aXor;
#pragma unroll
            for (int mf = 0; mf < 2; mf++) {
                u32 ad = b0 + (u32)((wm * 32 + mf * 16 + arl) * 128) + ka;
                ldsm4(ah[mf], ad);
                ldsm4(al[mf], ad + (u32)MT * 128);
            }
            u32 kb = ((u32)(ks * 32) + bK) ^ bXor;
            u32 bhC[NFC][2], blC[NFC][2], bhH[NFC][2], blH[NFC][2];
#pragma unroll
            for (int nf = 0; nf < NFC; nf++) {
                u32 bc = wB + (u32)((ncw + nf * 8 + brl) * 128) + kb;
                ldsm2(bhC[nf], bc); ldsm2(blC[nf], bc + 16384u);
                u32 bh = wB + (u32)((64 + ncw + nf * 8 + brl) * 128) + kb;
                ldsm2(bhH[nf], bh); ldsm2(blH[nf], bh + 16384u);
            }
#pragma unroll
            for (int mf = 0; mf < 2; mf++)
#pragma unroll
                for (int nf = 0; nf < NFC; nf++) {
                    mma16816(accC[mf][nf], ah[mf], bhC[nf]);
                    mma16816(accC[mf][nf], ah[mf], blC[nf]);
                    mma16816(accC[mf][nf], al[mf], bhC[nf]);
                    mma16816(accH[mf][nf], ah[mf], bhH[nf]);
                    mma16816(accH[mf][nf], ah[mf], blH[nf]);
                    mma16816(accH[mf][nf], al[mf], bhH[nf]);
                }
        }
        __syncthreads();
        if (ci + 2 < nchunks) issue(ci + 2, buf);
        buf ^= 1;
    }

    /* fused epilogue: s = sp + sig(c)*(act(h) - sp); fp32 + optional bf16 hi/lo image */
#pragma unroll
    for (int mf = 0; mf < 2; mf++)
#pragma unroll
        for (int nf = 0; nf < NFC; nf++) {
            int rb = m0 + wm * 32 + mf * 16 + (lid >> 2);
            int j = j0 + ncw + nf * 8 + (lid & 3) * 2;
#pragma unroll
            for (int hr = 0; hr < 2; hr++) {
                int r = rb + hr * 8;
                float cv0 = accC[mf][nf][hr * 2 + 0], cv1 = accC[mf][nf][hr * 2 + 1];
                float hv0 = accH[mf][nf][hr * 2 + 0], hv1 = accH[mf][nf][hr * 2 + 1];
                float2 spv = *(const float2*)(sp + (size_t)r * HH + j);
                float s0 = spv.x + sigf(cv0) * (actf(hv0, act) - spv.x);
                float s1 = spv.y + sigf(cv1) * (actf(hv1, act) - spv.y);
                *(float2*)(Sout + (size_t)r * HH + j) = make_float2(s0, s1);
                if (imgH) {
                    u32 hi, lo; split2(s0, s1, hi, lo);
                    u32 off = SWZ((u32)((r & 127) * 128 + (j & 63) * 2));
                    *(u32*)((char*)imgH + off) = hi;
                    *(u32*)((char*)imgL + off) = lo;
                }
            }
        }
}

/* ---------------- persistent kernel: all steps & phases ---------------- */
__global__ __launch_bounds__(NTHR, 1) void darts_mma(
    const float* __restrict__ inputs, const float* __restrict__ h0,
    float* __restrict__ out)
{
    extern __shared__ char smem[];
    const u32 sbase = smem_u32(smem);
    const int tid = threadIdx.x, bid = blockIdx.x;

    for (int t = 0; t < TT; t++) {
        const float* hp = t ? (out + (size_t)(t - 1) * BMH) : h0;

        /* Phase A: s0 over concat(x, h_prev), K=2048. 128 T32 tasks. act tanh. */
        {
            int m0 = (bid >> 4) * 32, nt = bid & 15, mtb = m0 >> 7, ro = (m0 & 127) * 8;
            run_tile<32>(sbase,
                g_Xh + (size_t)mtb * 16 * CHU, g_Xl + (size_t)mtb * 16 * CHU,
                g_Hh + (size_t)mtb * 16 * CHU, g_Hl + (size_t)mtb * 16 * CHU,
                16, 32, ro,
                g_W0h + (size_t)nt * 32 * CHU, g_W0l + (size_t)nt * 32 * CHU,
                hp, g_S[0],
                g_Sih + ((size_t)mtb * 16 + nt) * CHU,
                g_Sil + ((size_t)mtb * 16 + nt) * CHU, 2, m0, nt * 64);
        }
        gridbar();

        /* Phase B: s1 = f(s0, Ws0, sigmoid). 128 T32 tasks, K=1024. */
        {
            int m0 = (bid >> 4) * 32, nt = bid & 15, mtb = m0 >> 7, ro = (m0 & 127) * 8;
            run_tile<32>(sbase,
                g_Sih + (size_t)mtb * 16 * CHU, g_Sil + (size_t)mtb * 16 * CHU,
                (const uint4*)0, (const uint4*)0, 16, 16, ro,
                g_Wsh + (size_t)nt * 16 * CHU, g_Wsl + (size_t)nt * 16 * CHU,
                g_S[0], g_S[1],
                g_Sih + ((size_t)(32 + mtb * 16 + nt)) * CHU,
                g_Sil + ((size_t)(32 + mtb * 16 + nt)) * CHU, 0, m0, nt * 64);
        }
        gridbar();

        /* Phase C: s2 (bid<64), s3 (bid>=64) from s1. 128 T64 tasks, relu. */
        {
            int op = bid >> 6, sub = bid & 63;
            int m0 = (sub >> 4) * 64, nt = sub & 15, mtb = m0 >> 7, ro = (m0 & 127) * 8;
            int os = 2 + op;
            run_tile<64>(sbase,
                g_Sih + (size_t)(32 + mtb * 16) * CHU, g_Sil + (size_t)(32 + mtb * 16) * CHU,
                (const uint4*)0, (const uint4*)0, 16, 16, ro,
                g_Wsh + (size_t)((1 + op) * 256 + nt * 16) * CHU,
                g_Wsl + (size_t)((1 + op) * 256 + nt * 16) * CHU,
                g_S[1], g_S[os],
                g_Sih + ((size_t)(os * 32 + mtb * 16 + nt)) * CHU,
                g_Sil + ((size_t)(os * 32 + mtb * 16 + nt)) * CHU, 1, m0, nt * 64);
        }
        gridbar();

        /* Phase D: s5<-s2 / s7<-s3 (T64, tanh), then s4<-s1 (T32, identity). */
        {
            int op = bid >> 6, sub = bid & 63;
            int m0 = (sub >> 4) * 64, nt = sub & 15, mtb = m0 >> 7, ro = (m0 & 127) * 8;
            int is = op ? 3 : 2, os = op ? 7 : 5, wop = op ? 6 : 4;
            uint4* ih = op ? (uint4*)0 : g_Sih + ((size_t)(5 * 32 + mtb * 16 + nt)) * CHU;
            uint4* il = op ? (uint4*)0 : g_Sil + ((size_t)(5 * 32 + mtb * 16 + nt)) * CHU;
            run_tile<64>(sbase,
                g_Sih + (size_t)(is * 32 + mtb * 16) * CHU, g_Sil + (size_t)(is * 32 + mtb * 16) * CHU,
                (const uint4*)0, (const uint4*)0, 16, 16, ro,
                g_Wsh + (size_t)(wop * 256 + nt * 16) * CHU,
                g_Wsl + (size_t)(wop * 256 + nt * 16) * CHU,
                g_S[is], g_S[os], ih, il, 2, m0, nt * 64);

            int m0b = (bid >> 4) * 32, ntb = bid & 15, mtb2 = m0b >> 7, rob = (m0b & 127) * 8;
            run_tile<32>(sbase,
                g_Sih + (size_t)(32 + mtb2 * 16) * CHU, g_Sil + (size_t)(32 + mtb2 * 16) * CHU,
                (const uint4*)0, (const uint4*)0, 16, 16, rob,
                g_Wsh + (size_t)(3 * 256 + ntb * 16) * CHU,
                g_Wsl + (size_t)(3 * 256 + ntb * 16) * CHU,
                g_S[1], g_S[4], (uint4*)0, (uint4*)0, 3, m0b, ntb * 64);
        }
        gridbar();

        /* Phase E: s6<-s5 (sigmoid) / s8<-s5 (relu). 128 T64 tasks. */
        {
            int op = bid >> 6, sub = bid & 63;
            int m0 = (sub >> 4) * 64, nt = sub & 15, mtb = m0 >> 7, ro = (m0 & 127) * 8;
            int os = op ? 8 : 6, wop = op ? 7 : 5, a = op ? 1 : 0;
            run_tile<64>(sbase,
                g_Sih + (size_t)(5 * 32 + mtb * 16) * CHU, g_Sil + (size_t)(5 * 32 + mtb * 16) * CHU,
                (const uint4*)0, (const uint4*)0, 16, 16, ro,
                g_Wsh + (size_t)(wop * 256 + nt * 16) * CHU,
                g_Wsl + (size_t)(wop * 256 + nt * 16) * CHU,
                g_S[5], g_S[os], (uint4*)0, (uint4*)0, a, m0, nt * 64);
        }
        gridbar();

        /* Phase F: out[t] = mean(s1..s8); emit h image; convert x_{t+1} image. */
        {
            float* ot = out + (size_t)t * BMH;
            int uu = bid * NTHR + tid;               /* 32768 tasks of 8 floats */
            int m = uu >> 7, j = (uu & 127) * 8;
            float a[8] = {0.f, 0.f, 0.f, 0.f, 0.f, 0.f, 0.f, 0.f};
#pragma unroll
            for (int s = 1; s < 9; s++) {
                const float4* p = (const float4*)(&g_S[s][(size_t)m * HH + j]);
                float4 v0 = p[0], v1 = p[1];
                a[0] += v0.x; a[1] += v0.y; a[2] += v0.z; a[3] += v0.w;
                a[4] += v1.x; a[5] += v1.y; a[6] += v1.z; a[7] += v1.w;
            }
#pragma unroll
            for (int q = 0; q < 8; q++) a[q] *= 0.125f;
            float4* q4 = (float4*)(ot + (size_t)m * HH + j);
            q4[0] = make_float4(a[0], a[1], a[2], a[3]);
            q4[1] = make_float4(a[4], a[5], a[6], a[7]);
            {
                uint4 hi, lo; split8(a, hi, lo);
                u32 off = SWZ((u32)((m & 127) * 128 + (j & 63) * 2));
                size_t blk = ((size_t)(m >> 7) * 16 + (j >> 6)) * CHU;
                g_Hh[blk + (off >> 4)] = hi; g_Hl[blk + (off >> 4)] = lo;
            }
            if (t + 1 < TT) {
                const float4* p = (const float4*)(inputs + (size_t)(t + 1) * BMH + (size_t)m * HH + j);
                float4 v0 = p[0], v1 = p[1];
                float v[8] = {v0.x, v0.y, v0.z, v0.w, v1.x, v1.y, v1.z, v1.w};
                uint4 hi, lo; split8(v, hi, lo);
                u32 off = SWZ((u32)((m & 127) * 128 + (j & 63) * 2));
                size_t blk = ((size_t)(m >> 7) * 16 + (j >> 6)) * CHU;
                g_Xh[blk + (off >> 4)] = hi; g_Xl[blk + (off >> 4)] = lo;
            }
        }
        gridbar();
    }
}

extern "C" void kernel_launch(void* const* d_in, const int* in_sizes, int n_in,
                              void* d_out, int out_size)
{
    const float* inputs = (const float*)d_in[0];  /* [T, B, 1024] */
    const float* h0     = (const float*)d_in[1];  /* [B, 1024]    */
    const float* W0     = (const float*)d_in[2];  /* [2048, 2048] */
    const float* Ws     = (const float*)d_in[3];  /* [8, 1024, 2048] */
    float* out = (float*)d_out;                   /* [T, B, 1024] */

    cudaFuncSetAttribute(darts_mma, cudaFuncAttributeMaxDynamicSharedMemorySize, SMEMT);

    prep<<<2816, NTHR>>>(inputs, h0, W0, Ws);
    darts_mma<<<GBLK, NTHR, SMEMT>>>(inputs, h0, out);
}